// round 16
// baseline (speedup 1.0000x reference)
#include <cuda_runtime.h>
#include <cuda_fp16.h>
#include <cstdint>

// ---------------- scratch (device globals, fp16 single-term) ----------------
__device__ __align__(16) __half g_Xf[4096*1024];
__device__ __align__(16) __half g_Wf[3*1024*1024];
__device__ __align__(16) __half g_Qf[32*2048*64];
__device__ __align__(16) __half g_Kf[32*2048*64];
__device__ __align__(16) __half g_Vf[32*2048*64];

// ---------------- helpers ----------------
__device__ __forceinline__ uint32_t smem_u32(const void* p) {
    uint32_t a;
    asm("{ .reg .u64 t; cvta.to.shared.u64 t, %1; cvt.u32.u64 %0, t; }" : "=r"(a) : "l"(p));
    return a;
}
__device__ __forceinline__ uint32_t packh(float a, float b) {
    __half2 h = __floats2half2_rn(a, b);
    return *reinterpret_cast<uint32_t*>(&h);
}
__device__ __forceinline__ void ldsm_x4(uint32_t a, uint32_t& r0, uint32_t& r1,
                                        uint32_t& r2, uint32_t& r3) {
    asm volatile("ldmatrix.sync.aligned.m8n8.x4.shared.b16 {%0,%1,%2,%3}, [%4];"
        : "=r"(r0), "=r"(r1), "=r"(r2), "=r"(r3) : "r"(a));
}
__device__ __forceinline__ void ldsm_x4t(uint32_t a, uint32_t& r0, uint32_t& r1,
                                         uint32_t& r2, uint32_t& r3) {
    asm volatile("ldmatrix.sync.aligned.m8n8.x4.trans.shared.b16 {%0,%1,%2,%3}, [%4];"
        : "=r"(r0), "=r"(r1), "=r"(r2), "=r"(r3) : "r"(a));
}
__device__ __forceinline__ void mma16816(float* c, const uint32_t* a,
                                         uint32_t b0, uint32_t b1) {
    asm("mma.sync.aligned.m16n8k16.row.col.f32.f16.f16.f32 "
        "{%0,%1,%2,%3}, {%4,%5,%6,%7}, {%8,%9}, {%0,%1,%2,%3};"
        : "+f"(c[0]), "+f"(c[1]), "+f"(c[2]), "+f"(c[3])
        : "r"(a[0]), "r"(a[1]), "r"(a[2]), "r"(a[3]), "r"(b0), "r"(b1));
}
__device__ __forceinline__ void cpa16(uint32_t dst, const void* src) {
    asm volatile("cp.async.cg.shared.global [%0], [%1], 16;" :: "r"(dst), "l"(src));
}
__device__ __forceinline__ void cpcommit() { asm volatile("cp.async.commit_group;"); }
__device__ __forceinline__ void cpwait1()  { asm volatile("cp.async.wait_group 1;"); }
__device__ __forceinline__ void cpwait0()  { asm volatile("cp.async.wait_group 0;"); }

// swizzled byte offset within an 8KB region (64 rows x 128B), chunk c8 in 0..7
__device__ __forceinline__ uint32_t swoff(int r, int c8) {
    return (uint32_t)(((r << 3) + (c8 ^ (r & 7))) << 4);
}

// ---------------- prep: X fp32 -> fp16 ----------------
__global__ __launch_bounds__(256) void prep_x(const float* __restrict__ X) {
    size_t i = (size_t)blockIdx.x * 256 + threadIdx.x;   // 1M float4
    float4 v = ((const float4*)X)[i];
    ((uint2*)g_Xf)[i] = make_uint2(packh(v.x, v.y), packh(v.z, v.w));
}

// ---------------- prep: transpose W -> [mat][h*64+e][d], fp16 ----------------
__global__ __launch_bounds__(256) void prep_w(const float* __restrict__ Wq,
                                              const float* __restrict__ Wk,
                                              const float* __restrict__ Wv) {
    int z = blockIdx.z, mat = z >> 4, h = z & 15;
    const float* W = (mat == 0 ? Wq : (mat == 1 ? Wk : Wv)) + (size_t)h * 1024 * 64;
    __shared__ float t[32][33];
    int d0 = blockIdx.x * 32, e0 = blockIdx.y * 32;
    int tx = threadIdx.x, ty = threadIdx.y;
    #pragma unroll
    for (int k = 0; k < 4; k++)
        t[ty + 8 * k][tx] = W[(size_t)(d0 + ty + 8 * k) * 64 + e0 + tx];
    __syncthreads();
    __half* of = g_Wf + (size_t)mat * 1048576;
    #pragma unroll
    for (int k = 0; k < 4; k++) {
        int j = ty + 8 * k;
        of[(size_t)(h * 64 + e0 + j) * 1024 + d0 + tx] = __float2half(t[tx][j]);
    }
}

// ---------------- QKV GEMM: 128x128 CTA tile, fp16, k-chunk 64 (R13 winner) ----------------
#define QS_STAGE 32768
#define QKV_SMEM (2 * QS_STAGE)

__device__ __forceinline__ void qkv_prefetch(uint32_t s0, int stile, int octile,
                                             int kc, int tid, const __half* Bf) {
    #pragma unroll
    for (int i = tid; i < 2048; i += 256) {
        int idx = i & 1023;
        int r = idx >> 3, c8 = idx & 7;
        bool isB = (i >= 1024);
        const __half* src = isB ? Bf : g_Xf;
        int gr = (isB ? octile : stile) * 128 + r;
        size_t g = (size_t)gr * 1024 + kc * 64 + c8 * 8;
        uint32_t d = s0 + (isB ? 16384u : 0u) + ((r >= 64) ? 8192u : 0u) + swoff(r & 63, c8);
        cpa16(d, src + g);
    }
}

__global__ __launch_bounds__(256, 2) void qkv_mm(const float* __restrict__ bq,
                                                 const float* __restrict__ bk,
                                                 const float* __restrict__ bv) {
    extern __shared__ __align__(16) __half smq[];
    uint32_t sb = smem_u32(smq);
    int tid = threadIdx.x, lane = tid & 31, wid = tid >> 5;
    int stile = blockIdx.x, octile = blockIdx.y, mat = blockIdx.z;
    int wm = wid >> 1, wn = wid & 1;   // 4x2 warps: 32 rows x 64 cols each
    int lm = lane & 15;

    const __half* Bf = g_Wf + (size_t)mat * 1048576;

    float C[2][8][4] = {};

    qkv_prefetch(sb, stile, octile, 0, tid, Bf);
    cpcommit();

    for (int kc = 0; kc < 16; kc++) {
        if (kc < 15) {
            qkv_prefetch(sb + ((kc + 1) & 1) * QS_STAGE, stile, octile, kc + 1, tid, Bf);
            cpcommit();
            cpwait1();
        } else {
            cpwait0();
        }
        __syncthreads();
        uint32_t sA = sb + (kc & 1) * QS_STAGE;
        uint32_t sB = sA + 16384;

        #pragma unroll
        for (int ks = 0; ks < 4; ks++) {
            uint32_t af[2][4];
            #pragma unroll
            for (int mt = 0; mt < 2; mt++) {
                int r = wm * 32 + mt * 16 + lm;
                uint32_t reg0 = (r >= 64) ? 8192u : 0u;
                int c8 = ks * 2 + (lane >> 4);
                ldsm_x4(sA + reg0 + swoff(r & 63, c8),
                        af[mt][0], af[mt][1], af[mt][2], af[mt][3]);
            }
            #pragma unroll
            for (int ntp = 0; ntp < 4; ntp++) {
                int rB = ntp * 16 + ((lane >> 4) << 3) + (lane & 7);
                int c8 = ks * 2 + ((lane >> 3) & 1);
                uint32_t regB = wn * 8192u;
                uint32_t h0, h1, h2, h3;
                ldsm_x4(sB + regB + swoff(rB, c8), h0, h1, h2, h3);
                #pragma unroll
                for (int mt = 0; mt < 2; mt++) {
                    mma16816(C[mt][2 * ntp],     af[mt], h0, h1);
                    mma16816(C[mt][2 * ntp + 1], af[mt], h2, h3);
                }
            }
        }
        __syncthreads();
    }

    const float* bias = (mat == 0 ? bq : (mat == 1 ? bk : bv));
    float scale = (mat == 0) ? 0.125f : 1.0f;
    __half* Df = (mat == 0 ? g_Qf : (mat == 1 ? g_Kf : g_Vf));
    #pragma unroll
    for (int mt = 0; mt < 2; mt++) {
        #pragma unroll
        for (int nt = 0; nt < 8; nt++) {
            int col = octile * 128 + wn * 64 + nt * 8 + 2 * (lane & 3);
            float b0 = __ldg(bias + col), b1 = __ldg(bias + col + 1);
            int hh = col >> 6, e = col & 63;
            #pragma unroll
            for (int hf = 0; hf < 2; hf++) {
                int row = stile * 128 + wm * 32 + mt * 16 + (lane >> 2) + 8 * hf;
                float v0 = (C[mt][nt][2 * hf + 0] + b0) * scale;
                float v1 = (C[mt][nt][2 * hf + 1] + b1) * scale;
                int b = row >> 11, s = row & 2047;
                size_t o = ((size_t)(b * 16 + hh) * 2048 + s) * 64 + e;
                *(uint32_t*)&Df[o] = packh(v0, v1);
            }
        }
    }
}

// ---------------- attention: fp16, 8 warps x 32 q-rows (256-row CTA) ----------------
// smem: Q 4 regions @0..24576 (32KB); stages @32768 + st*16384: K @+0, V @+8192
#define A_STAGE 16384
#define A_SMEM (32768 + 2 * A_STAGE)   // 64KB -> 2 CTAs/SM

__device__ __forceinline__ void attn_prefetch(uint32_t s0, int tid,
                                              const __half* Kf, const __half* Vf,
                                              bool full) {
    #pragma unroll
    for (int i = tid; i < 512; i += 256) {
        int r = i >> 3, c8 = i & 7;
        uint32_t d = swoff(r, c8);
        size_t g = (size_t)r * 64 + c8 * 8;
        cpa16(s0 + d, Kf + g);
        if (full) cpa16(s0 + 8192 + d, Vf + g);
    }
}

__global__ __launch_bounds__(256, 2) void attn(float* __restrict__ out) {
    extern __shared__ __align__(16) char sm[];
    uint32_t sb = smem_u32(sm);
    int tid = threadIdx.x, lane = tid & 31, w = tid >> 5;
    int bh = blockIdx.x >> 3, qt = 7 - (blockIdx.x & 7);   // heavy-first
    int b = bh >> 4, h = bh & 15;
    int lm = lane & 15;

    const __half* Qf  = g_Qf + ((size_t)bh * 2048 + qt * 256) * 64;
    const __half* Kfb = g_Kf + (size_t)bh * 2048 * 64;
    const __half* Vfb = g_Vf + (size_t)bh * 2048 * 64;

    // Q load (256x64 fp16, 4 regions - never recycled)
    #pragma unroll
    for (int i = tid; i < 2048; i += 256) {
        int r = i >> 3, c8 = i & 7;
        uint32_t d = (uint32_t)(r >> 6) * 8192u + swoff(r & 63, c8);
        cpa16(sb + d, Qf + (size_t)r * 64 + c8 * 8);
    }
    cpcommit();

    int kmax = 4 * qt + 3;
    attn_prefetch(sb + 32768, tid, Kfb, Vfb, true);   // kt=0 always live
    cpcommit();

    cpwait1();          // Q group done
    __syncthreads();

    // Q fragments: warp's 32 rows (2 x 16-row m-subtiles)
    uint32_t qf[2][4][4];
    #pragma unroll
    for (int mt = 0; mt < 2; mt++) {
        int r = w * 32 + mt * 16 + lm;
        uint32_t qreg = (uint32_t)(r >> 6) * 8192u;
        int rr = r & 63;
        #pragma unroll
        for (int ks = 0; ks < 4; ks++) {
            int c8 = ks * 2 + (lane >> 4);
            ldsm_x4(sb + qreg + swoff(rr, c8),
                    qf[mt][ks][0], qf[mt][ks][1], qf[mt][ks][2], qf[mt][ks][3]);
        }
    }

    float O[2][8][4] = {};
    float lsum[2][2] = {};

    for (int kt = 0; kt < 32; kt++) {
        if (kt < 31) {
            size_t off = (size_t)(kt + 1) * 64 * 64;
            attn_prefetch(sb + 32768 + ((kt + 1) & 1) * A_STAGE, tid,
                          Kfb + off, Vfb + off, (kt + 1) <= kmax);
            cpcommit();
            cpwait1();
        } else {
            cpwait0();
        }
        __syncthreads();

        uint32_t sK = sb + 32768 + (kt & 1) * A_STAGE;
        uint32_t sV = sK + 8192;
        bool live = (kt <= kmax);
        bool diag = ((kt >> 2) == qt);   // tiles straddling the diagonal
        int cb = kt * 64 + 2 * (lane & 3);

        #pragma unroll
        for (int k2 = 0; k2 < 4; k2++) {
            // ---- S slice: 32 rows x 16 cols (K fragment reused across both mt)
            float Sc[2][2][4] = {};
            #pragma unroll
            for (int ks = 0; ks < 4; ks++) {
                int row = k2 * 16 + ((lane >> 4) << 3) + (lane & 7);
                int c8 = ks * 2 + ((lane >> 3) & 1);
                uint32_t h0, h1, h2, h3;
                ldsm_x4(sK + swoff(row, c8), h0, h1, h2, h3);
                #pragma unroll
                for (int mt = 0; mt < 2; mt++) {
                    mma16816(Sc[mt][0], qf[mt][ks], h0, h1);
                    mma16816(Sc[mt][1], qf[mt][ks], h2, h3);
                }
            }
            // ---- exp on MUFU + full-row lsum (mask only on diagonal tiles)
            #pragma unroll
            for (int mt = 0; mt < 2; mt++)
                #pragma unroll
                for (int ntl = 0; ntl < 2; ntl++)
                    #pragma unroll
                    for (int hf = 0; hf < 2; hf++) {
                        float e0 = __expf(Sc[mt][ntl][2 * hf + 0]);
                        float e1 = __expf(Sc[mt][ntl][2 * hf + 1]);
                        lsum[mt][hf] += e0 + e1;
                        Sc[mt][ntl][2 * hf + 0] = e0;
                        Sc[mt][ntl][2 * hf + 1] = e1;
                    }
            if (diag) {   // post-softmax tril mask, numerator only
                #pragma unroll
                for (int mt = 0; mt < 2; mt++) {
                    int rb = qt * 256 + w * 32 + mt * 16 + (lane >> 2);
                    #pragma unroll
                    for (int ntl = 0; ntl < 2; ntl++) {
                        int colg = cb + k2 * 16 + ntl * 8;
                        #pragma unroll
                        for (int hf = 0; hf < 2; hf++) {
                            int rg = rb + 8 * hf;
                            if (colg     > rg) Sc[mt][ntl][2 * hf + 0] = 0.f;
                            if (colg + 1 > rg) Sc[mt][ntl][2 * hf + 1] = 0.f;
                        }
                    }
                }
            }
            // ---- PV for this 16-wide k-slice (V fragment reused across both mt)
            if (live) {
                uint32_t ph[2][4];
                #pragma unroll
                for (int mt = 0; mt < 2; mt++) {
                    ph[mt][0] = packh(Sc[mt][0][0], Sc[mt][0][1]);
                    ph[mt][1] = packh(Sc[mt][0][2], Sc[mt][0][3]);
                    ph[mt][2] = packh(Sc[mt][1][0], Sc[mt][1][1]);
                    ph[mt][3] = packh(Sc[mt][1][2], Sc[mt][1][3]);
                }
                int row = k2 * 16 + lm;
                #pragma unroll
                for (int ntp = 0; ntp < 4; ntp++) {
                    uint32_t v0, v1, v2, v3;
                    ldsm_x4t(sV + swoff(row, ntp * 2 + (lane >> 4)), v0, v1, v2, v3);
                    #pragma unroll
                    for (int mt = 0; mt < 2; mt++) {
                        mma16816(O[mt][2 * ntp],     ph[mt], v0, v1);
                        mma16816(O[mt][2 * ntp + 1], ph[mt], v2, v3);
                    }
                }
            }
        }
        __syncthreads();   // compute done before next prefetch overwrites other stage
    }

    // ---- row denominators: quad butterfly (warp-local rows)
    #pragma unroll
    for (int mt = 0; mt < 2; mt++)
        #pragma unroll
        for (int hf = 0; hf < 2; hf++) {
            lsum[mt][hf] += __shfl_xor_sync(0xffffffffu, lsum[mt][hf], 1);
            lsum[mt][hf] += __shfl_xor_sync(0xffffffffu, lsum[mt][hf], 2);
        }

    // ---- write out
    #pragma unroll
    for (int mt = 0; mt < 2; mt++)
        #pragma unroll
        for (int hf = 0; hf < 2; hf++) {
            float inv = 1.0f / lsum[mt][hf];
            int rg = qt * 256 + w * 32 + mt * 16 + (lane >> 2) + 8 * hf;
            float* ob = out + ((size_t)b * 2048 + rg) * 1024 + h * 64;
            #pragma unroll
            for (int nt = 0; nt < 8; nt++) {
                int c = nt * 8 + 2 * (lane & 3);
                *(float2*)&ob[c] = make_float2(O[mt][nt][2 * hf] * inv,
                                               O[mt][nt][2 * hf + 1] * inv);
            }
        }
}

extern "C" void kernel_launch(void* const* d_in, const int* in_sizes, int n_in,
                              void* d_out, int out_size) {
    const float* X  = (const float*)d_in[0];
    const float* Wq = (const float*)d_in[1];
    const float* bq = (const float*)d_in[2];
    const float* Wk = (const float*)d_in[3];
    const float* bk = (const float*)d_in[4];
    const float* Wv = (const float*)d_in[5];
    const float* bv = (const float*)d_in[6];

    cudaFuncSetAttribute(qkv_mm, cudaFuncAttributeMaxDynamicSharedMemorySize, QKV_SMEM);
    cudaFuncSetAttribute(attn,   cudaFuncAttributeMaxDynamicSharedMemorySize, A_SMEM);

    prep_x<<<4096, 256>>>(X);
    prep_w<<<dim3(32, 2, 48), dim3(32, 8)>>>(Wq, Wk, Wv);
    qkv_mm<<<dim3(32, 8, 3), 256, QKV_SMEM>>>(bq, bk, bv);
    attn<<<256, 256, A_SMEM>>>((float*)d_out);
}

// round 17
// speedup vs baseline: 1.1095x; 1.1095x over previous
#include <cuda_runtime.h>
#include <cuda_fp16.h>
#include <cstdint>

// ---------------- scratch (device globals, fp16 single-term) ----------------
__device__ __align__(16) __half g_Xf[4096*1024];
__device__ __align__(16) __half g_Wf[3*1024*1024];
__device__ __align__(16) __half g_Qf[32*2048*64];
__device__ __align__(16) __half g_Kf[32*2048*64];
__device__ __align__(16) __half g_Vf[32*2048*64];

// ---------------- helpers ----------------
__device__ __forceinline__ uint32_t smem_u32(const void* p) {
    uint32_t a;
    asm("{ .reg .u64 t; cvta.to.shared.u64 t, %1; cvt.u32.u64 %0, t; }" : "=r"(a) : "l"(p));
    return a;
}
__device__ __forceinline__ uint32_t packh(float a, float b) {
    __half2 h = __floats2half2_rn(a, b);
    return *reinterpret_cast<uint32_t*>(&h);
}
__device__ __forceinline__ void ldsm_x4(uint32_t a, uint32_t& r0, uint32_t& r1,
                                        uint32_t& r2, uint32_t& r3) {
    asm volatile("ldmatrix.sync.aligned.m8n8.x4.shared.b16 {%0,%1,%2,%3}, [%4];"
        : "=r"(r0), "=r"(r1), "=r"(r2), "=r"(r3) : "r"(a));
}
__device__ __forceinline__ void ldsm_x4t(uint32_t a, uint32_t& r0, uint32_t& r1,
                                         uint32_t& r2, uint32_t& r3) {
    asm volatile("ldmatrix.sync.aligned.m8n8.x4.trans.shared.b16 {%0,%1,%2,%3}, [%4];"
        : "=r"(r0), "=r"(r1), "=r"(r2), "=r"(r3) : "r"(a));
}
__device__ __forceinline__ void mma16816(float* c, const uint32_t* a,
                                         uint32_t b0, uint32_t b1) {
    asm("mma.sync.aligned.m16n8k16.row.col.f32.f16.f16.f32 "
        "{%0,%1,%2,%3}, {%4,%5,%6,%7}, {%8,%9}, {%0,%1,%2,%3};"
        : "+f"(c[0]), "+f"(c[1]), "+f"(c[2]), "+f"(c[3])
        : "r"(a[0]), "r"(a[1]), "r"(a[2]), "r"(a[3]), "r"(b0), "r"(b1));
}
__device__ __forceinline__ void cpa16(uint32_t dst, const void* src) {
    asm volatile("cp.async.cg.shared.global [%0], [%1], 16;" :: "r"(dst), "l"(src));
}
__device__ __forceinline__ void cpcommit() { asm volatile("cp.async.commit_group;"); }
__device__ __forceinline__ void cpwait2()  { asm volatile("cp.async.wait_group 2;"); }
__device__ __forceinline__ void cpwait1()  { asm volatile("cp.async.wait_group 1;"); }
__device__ __forceinline__ void cpwait0()  { asm volatile("cp.async.wait_group 0;"); }

// swizzled byte offset within an 8KB region (64 rows x 128B), chunk c8 in 0..7
__device__ __forceinline__ uint32_t swoff(int r, int c8) {
    return (uint32_t)(((r << 3) + (c8 ^ (r & 7))) << 4);
}

// ---------------- prep: X fp32 -> fp16 ----------------
__global__ __launch_bounds__(256) void prep_x(const float* __restrict__ X) {
    size_t i = (size_t)blockIdx.x * 256 + threadIdx.x;   // 1M float4
    float4 v = ((const float4*)X)[i];
    ((uint2*)g_Xf)[i] = make_uint2(packh(v.x, v.y), packh(v.z, v.w));
}

// ---------------- prep: transpose W -> [mat][h*64+e][d], fp16 ----------------
__global__ __launch_bounds__(256) void prep_w(const float* __restrict__ Wq,
                                              const float* __restrict__ Wk,
                                              const float* __restrict__ Wv) {
    int z = blockIdx.z, mat = z >> 4, h = z & 15;
    const float* W = (mat == 0 ? Wq : (mat == 1 ? Wk : Wv)) + (size_t)h * 1024 * 64;
    __shared__ float t[32][33];
    int d0 = blockIdx.x * 32, e0 = blockIdx.y * 32;
    int tx = threadIdx.x, ty = threadIdx.y;
    #pragma unroll
    for (int k = 0; k < 4; k++)
        t[ty + 8 * k][tx] = W[(size_t)(d0 + ty + 8 * k) * 64 + e0 + tx];
    __syncthreads();
    __half* of = g_Wf + (size_t)mat * 1048576;
    #pragma unroll
    for (int k = 0; k < 4; k++) {
        int j = ty + 8 * k;
        of[(size_t)(h * 64 + e0 + j) * 1024 + d0 + tx] = __float2half(t[tx][j]);
    }
}

// ---------------- QKV GEMM: 128x128 CTA tile, fp16, k-chunk 64 (R13 winner) ----------------
#define QS_STAGE 32768
#define QKV_SMEM (2 * QS_STAGE)

__device__ __forceinline__ void qkv_prefetch(uint32_t s0, int stile, int octile,
                                             int kc, int tid, const __half* Bf) {
    #pragma unroll
    for (int i = tid; i < 2048; i += 256) {
        int idx = i & 1023;
        int r = idx >> 3, c8 = idx & 7;
        bool isB = (i >= 1024);
        const __half* src = isB ? Bf : g_Xf;
        int gr = (isB ? octile : stile) * 128 + r;
        size_t g = (size_t)gr * 1024 + kc * 64 + c8 * 8;
        uint32_t d = s0 + (isB ? 16384u : 0u) + ((r >= 64) ? 8192u : 0u) + swoff(r & 63, c8);
        cpa16(d, src + g);
    }
}

__global__ __launch_bounds__(256, 2) void qkv_mm(const float* __restrict__ bq,
                                                 const float* __restrict__ bk,
                                                 const float* __restrict__ bv) {
    extern __shared__ __align__(16) __half smq[];
    uint32_t sb = smem_u32(smq);
    int tid = threadIdx.x, lane = tid & 31, wid = tid >> 5;
    int stile = blockIdx.x, octile = blockIdx.y, mat = blockIdx.z;
    int wm = wid >> 1, wn = wid & 1;   // 4x2 warps: 32 rows x 64 cols each
    int lm = lane & 15;

    const __half* Bf = g_Wf + (size_t)mat * 1048576;

    float C[2][8][4] = {};

    qkv_prefetch(sb, stile, octile, 0, tid, Bf);
    cpcommit();

    for (int kc = 0; kc < 16; kc++) {
        if (kc < 15) {
            qkv_prefetch(sb + ((kc + 1) & 1) * QS_STAGE, stile, octile, kc + 1, tid, Bf);
            cpcommit();
            cpwait1();
        } else {
            cpwait0();
        }
        __syncthreads();
        uint32_t sA = sb + (kc & 1) * QS_STAGE;
        uint32_t sB = sA + 16384;

        #pragma unroll
        for (int ks = 0; ks < 4; ks++) {
            uint32_t af[2][4];
            #pragma unroll
            for (int mt = 0; mt < 2; mt++) {
                int r = wm * 32 + mt * 16 + lm;
                uint32_t reg0 = (r >= 64) ? 8192u : 0u;
                int c8 = ks * 2 + (lane >> 4);
                ldsm_x4(sA + reg0 + swoff(r & 63, c8),
                        af[mt][0], af[mt][1], af[mt][2], af[mt][3]);
            }
            #pragma unroll
            for (int ntp = 0; ntp < 4; ntp++) {
                int rB = ntp * 16 + ((lane >> 4) << 3) + (lane & 7);
                int c8 = ks * 2 + ((lane >> 3) & 1);
                uint32_t regB = wn * 8192u;
                uint32_t h0, h1, h2, h3;
                ldsm_x4(sB + regB + swoff(rB, c8), h0, h1, h2, h3);
                #pragma unroll
                for (int mt = 0; mt < 2; mt++) {
                    mma16816(C[mt][2 * ntp],     af[mt], h0, h1);
                    mma16816(C[mt][2 * ntp + 1], af[mt], h2, h3);
                }
            }
        }
        __syncthreads();
    }

    const float* bias = (mat == 0 ? bq : (mat == 1 ? bk : bv));
    float scale = (mat == 0) ? 0.125f : 1.0f;
    __half* Df = (mat == 0 ? g_Qf : (mat == 1 ? g_Kf : g_Vf));
    #pragma unroll
    for (int mt = 0; mt < 2; mt++) {
        #pragma unroll
        for (int nt = 0; nt < 8; nt++) {
            int col = octile * 128 + wn * 64 + nt * 8 + 2 * (lane & 3);
            float b0 = __ldg(bias + col), b1 = __ldg(bias + col + 1);
            int hh = col >> 6, e = col & 63;
            #pragma unroll
            for (int hf = 0; hf < 2; hf++) {
                int row = stile * 128 + wm * 32 + mt * 16 + (lane >> 2) + 8 * hf;
                float v0 = (C[mt][nt][2 * hf + 0] + b0) * scale;
                float v1 = (C[mt][nt][2 * hf + 1] + b1) * scale;
                int b = row >> 11, s = row & 2047;
                size_t o = ((size_t)(b * 16 + hh) * 2048 + s) * 64 + e;
                *(uint32_t*)&Df[o] = packh(v0, v1);
            }
        }
    }
}

// ---------------- attention: R13 structure + 3-stage cp.async ring ----------------
// smem: Q region0 @0, Q region1 @8192; stages @16384 + st*16384: K @+0, V @+8192
#define A_STAGE 16384
#define A_SMEM (16384 + 3 * A_STAGE)   // 64KB -> 2 CTAs/SM (regs bind at 2)

__device__ __forceinline__ void attn_prefetch(uint32_t s0, int tid,
                                              const __half* Kf, const __half* Vf,
                                              bool full) {
    #pragma unroll
    for (int i = tid; i < 512; i += 256) {
        int r = i >> 3, c8 = i & 7;
        uint32_t d = swoff(r, c8);
        size_t g = (size_t)r * 64 + c8 * 8;
        cpa16(s0 + d, Kf + g);
        if (full) cpa16(s0 + 8192 + d, Vf + g);
    }
}

// S slice (16 rows x 16 cols), single fp16 term
__device__ __forceinline__ void compS(uint32_t sK, int k2, int lane,
                                      const uint32_t qf[4][4], float S[2][4]) {
    #pragma unroll
    for (int z = 0; z < 4; z++) { S[0][z] = 0.f; S[1][z] = 0.f; }
    #pragma unroll
    for (int ks = 0; ks < 4; ks++) {
        int row = k2 * 16 + ((lane >> 4) << 3) + (lane & 7);
        int c8 = ks * 2 + ((lane >> 3) & 1);
        uint32_t h0, h1, h2, h3;
        ldsm_x4(sK + swoff(row, c8), h0, h1, h2, h3);
        mma16816(S[0], qf[ks], h0, h1);
        mma16816(S[1], qf[ks], h2, h3);
    }
}

__global__ __launch_bounds__(256, 2) void attn(float* __restrict__ out) {
    extern __shared__ __align__(16) char sm[];
    uint32_t sb = smem_u32(sm);
    int tid = threadIdx.x, lane = tid & 31, w = tid >> 5;
    int bh = blockIdx.x >> 4, qt = 15 - (blockIdx.x & 15);   // heavy-first
    int b = bh >> 4, h = bh & 15;
    int lm = lane & 15;

    const __half* Qf  = g_Qf + ((size_t)bh * 2048 + qt * 128) * 64;
    const __half* Kfb = g_Kf + (size_t)bh * 2048 * 64;
    const __half* Vfb = g_Vf + (size_t)bh * 2048 * 64;

    // Q load (128x64 fp16, own region - never recycled)  [group: Q]
    #pragma unroll
    for (int i = tid; i < 1024; i += 256) {
        int r = i >> 3, c8 = i & 7;
        uint32_t d = ((r >= 64) ? 8192u : 0u) + swoff(r & 63, c8);
        cpa16(sb + d, Qf + (size_t)r * 64 + c8 * 8);
    }
    cpcommit();

    int kmax = 2 * qt + 1;
    // prime two stages [groups: kt=0, kt=1]
    attn_prefetch(sb + 16384, tid, Kfb, Vfb, true);
    cpcommit();
    attn_prefetch(sb + 16384 + A_STAGE, tid, Kfb + 64 * 64, Vfb + 64 * 64, 1 <= kmax);
    cpcommit();

    cpwait2();          // Q group done (two stage groups may remain in flight)
    __syncthreads();

    uint32_t qf[4][4];
    {
        int r = w * 16 + lm;
        uint32_t qreg = (r >= 64) ? 8192u : 0u;
        int rr = r & 63;
        #pragma unroll
        for (int ks = 0; ks < 4; ks++) {
            int c8 = ks * 2 + (lane >> 4);
            ldsm_x4(sb + qreg + swoff(rr, c8),
                    qf[ks][0], qf[ks][1], qf[ks][2], qf[ks][3]);
        }
    }

    float O[8][4] = {};
    float lsumA[2] = {}, lsumB[2] = {};
    int rbase = qt * 128 + w * 16 + (lane >> 2);

    for (int kt = 0; kt < 32; kt++) {
        if (kt + 2 < 32) {
            size_t off = (size_t)(kt + 2) * 64 * 64;
            attn_prefetch(sb + 16384 + (uint32_t)((kt + 2) % 3) * A_STAGE, tid,
                          Kfb + off, Vfb + off, (kt + 2) <= kmax);
            cpcommit();
            cpwait2();     // stage kt complete (kt+1, kt+2 may be in flight)
        } else if (kt + 1 < 32) {
            cpwait1();
        } else {
            cpwait0();
        }
        __syncthreads();

        uint32_t sK = sb + 16384 + (uint32_t)(kt % 3) * A_STAGE;
        uint32_t sV = sK + 8192;
        bool live = (kt <= kmax);
        bool diag = live && (kt >= 2 * qt);   // tiles straddling the diagonal
        int cb = kt * 64 + 2 * (lane & 3);

        float Sc[2][4];
        compS(sK, 0, lane, qf, Sc);

        #pragma unroll
        for (int k2 = 0; k2 < 4; k2++) {
            // software pipeline: next slice's S MMAs overlap exp/PV of current
            float Sn[2][4];
            if (k2 < 3) compS(sK, k2 + 1, lane, qf, Sn);

            // ---- exp on MUFU + full-row lsum (mask only on diagonal tiles)
            #pragma unroll
            for (int ntl = 0; ntl < 2; ntl++) {
                #pragma unroll
                for (int hf = 0; hf < 2; hf++) {
                    float e0 = __expf(Sc[ntl][2 * hf + 0]);
                    float e1 = __expf(Sc[ntl][2 * hf + 1]);
                    lsumA[hf] += e0;
                    lsumB[hf] += e1;
                    Sc[ntl][2 * hf + 0] = e0;
                    Sc[ntl][2 * hf + 1] = e1;
                }
            }
            if (diag) {   // post-softmax tril mask, numerator only
                #pragma unroll
                for (int ntl = 0; ntl < 2; ntl++) {
                    int colg = cb + k2 * 16 + ntl * 8;
                    #pragma unroll
                    for (int hf = 0; hf < 2; hf++) {
                        int rg = rbase + 8 * hf;
                        if (colg     > rg) Sc[ntl][2 * hf + 0] = 0.f;
                        if (colg + 1 > rg) Sc[ntl][2 * hf + 1] = 0.f;
                    }
                }
            }
            // ---- PV for this 16-wide k-slice (V fragments double-buffered)
            if (live) {
                uint32_t ph[4];
                ph[0] = packh(Sc[0][0], Sc[0][1]);
                ph[1] = packh(Sc[0][2], Sc[0][3]);
                ph[2] = packh(Sc[1][0], Sc[1][1]);
                ph[3] = packh(Sc[1][2], Sc[1][3]);
                int row = k2 * 16 + lm;
                uint32_t vA[4];
                ldsm_x4t(sV + swoff(row, (lane >> 4)), vA[0], vA[1], vA[2], vA[3]);
                #pragma unroll
                for (int ntp = 0; ntp < 4; ntp++) {
                    uint32_t vB[4];
                    if (ntp < 3)
                        ldsm_x4t(sV + swoff(row, (ntp + 1) * 2 + (lane >> 4)),
                                 vB[0], vB[1], vB[2], vB[3]);
                    mma16816(O[2 * ntp],     ph, vA[0], vA[1]);
                    mma16816(O[2 * ntp + 1], ph, vA[2], vA[3]);
                    if (ntp < 3) {
                        #pragma unroll
                        for (int z = 0; z < 4; z++) vA[z] = vB[z];
                    }
                }
            }
            if (k2 < 3) {
                #pragma unroll
                for (int ntl = 0; ntl < 2; ntl++)
                    #pragma unroll
                    for (int z = 0; z < 4; z++) Sc[ntl][z] = Sn[ntl][z];
            }
        }
        __syncthreads();   // compute(kt) done before iter kt+1 prefetches stage kt%3
    }

    // ---- row denominators: combine split chains + quad butterfly
    float lsum[2];
    #pragma unroll
    for (int hf = 0; hf < 2; hf++) {
        lsum[hf] = lsumA[hf] + lsumB[hf];
        lsum[hf] += __shfl_xor_sync(0xffffffffu, lsum[hf], 1);
        lsum[hf] += __shfl_xor_sync(0xffffffffu, lsum[hf], 2);
    }

    // ---- write out
    #pragma unroll
    for (int hf = 0; hf < 2; hf++) {
        float inv = 1.0f / lsum[hf];
        int rg = rbase + 8 * hf;
        float* ob = out + ((size_t)b * 2048 + rg) * 1024 + h * 64;
        #pragma unroll
        for (int nt = 0; nt < 8; nt++) {
            int c = nt * 8 + 2 * (lane & 3);
            *(float2*)&ob[c] = make_float2(O[nt][2 * hf] * inv, O[nt][2 * hf + 1] * inv);
        }
    }
}

extern "C" void kernel_launch(void* const* d_in, const int* in_sizes, int n_in,
                              void* d_out, int out_size) {
    const float* X  = (const float*)d_in[0];
    const float* Wq = (const float*)d_in[1];
    const float* bq = (const float*)d_in[2];
    const float* Wk = (const float*)d_in[3];
    const float* bk = (const float*)d_in[4];
    const float* Wv = (const float*)d_in[5];
    const float* bv = (const float*)d_in[6];

    cudaFuncSetAttribute(qkv_mm, cudaFuncAttributeMaxDynamicSharedMemorySize, QKV_SMEM);
    cudaFuncSetAttribute(attn,   cudaFuncAttributeMaxDynamicSharedMemorySize, A_SMEM);

    prep_x<<<4096, 256>>>(X);
    prep_w<<<dim3(32, 2, 48), dim3(32, 8)>>>(Wq, Wk, Wv);
    qkv_mm<<<dim3(32, 8, 3), 256, QKV_SMEM>>>(bq, bk, bv);
    attn<<<512, 256, A_SMEM>>>((float*)d_out);
}